// round 12
// baseline (speedup 1.0000x reference)
#include <cuda_runtime.h>
#include <cuda_bf16.h>
#include <stdint.h>
#include <math.h>

// Problem shape (fixed by the dataset)
#define TOK 8192          // B*S tokens
#define HDIM 1024
#define NEXP 8
#define IDIM 4096
#define NASSIGN (TOK*2)

// ------------- device scratch (TOTAL 335 MB: the proven envelope) -------------
__device__ int   g_counts[NEXP];
__device__ int   g_cursor[NEXP];
__device__ int   g_offset[NEXP];
__device__ int   g_rows[NASSIGN];
__device__ int   g_dest[NASSIGN];
__device__ float g_wgt[NASSIGN];
__device__ int   g_tope[NASSIGN];
__device__ float g_topw[NASSIGN];
// h stored as bf16 hi/lo planes, packed 2 cols per uint32 (replaces fp32 hbuf; same bytes)
__device__ uint32_t g_hbh[(size_t)NASSIGN * IDIM / 2];  // 134 MB
__device__ uint32_t g_hbl[(size_t)NASSIGN * IDIM / 2];  // 134 MB
__device__ float    g_ybuf[(size_t)NASSIGN * HDIM];     // 67 MB

// ---------------- helpers ----------------
__device__ __forceinline__ uint32_t smem_u32(const void* p) {
    uint32_t a;
    asm("{ .reg .u64 t; cvta.to.shared.u64 t, %1; cvt.u32.u64 %0, t; }" : "=r"(a) : "l"(p));
    return a;
}
__device__ __forceinline__ void ldm4(uint32_t addr, uint32_t* r) {
    asm volatile("ldmatrix.sync.aligned.m8n8.x4.shared.b16 {%0,%1,%2,%3}, [%4];\n"
        : "=r"(r[0]), "=r"(r[1]), "=r"(r[2]), "=r"(r[3]) : "r"(addr));
}
__device__ __forceinline__ void mma_bf16(float* c, const uint32_t* a, uint32_t b0, uint32_t b1) {
    asm volatile(
        "mma.sync.aligned.m16n8k16.row.col.f32.bf16.bf16.f32 "
        "{%0,%1,%2,%3}, {%4,%5,%6,%7}, {%8,%9}, {%0,%1,%2,%3};\n"
        : "+f"(c[0]), "+f"(c[1]), "+f"(c[2]), "+f"(c[3])
        : "r"(a[0]), "r"(a[1]), "r"(a[2]), "r"(a[3]), "r"(b0), "r"(b1));
}
__device__ __forceinline__ uint32_t pack2(__nv_bfloat16 a, __nv_bfloat16 b) {
    __nv_bfloat162 t = __halves2bfloat162(a, b);
    return *reinterpret_cast<uint32_t*>(&t);
}
__device__ __forceinline__ void split32(float f, __nv_bfloat16& h, __nv_bfloat16& l) {
    h = __float2bfloat16_rn(f);
    l = __float2bfloat16_rn(f - __bfloat162float(h));
}

// ---------------- routing kernels (proven) ----------------
__global__ void init_kernel() {
    int i = threadIdx.x;
    if (i < NEXP) { g_counts[i] = 0; g_cursor[i] = 0; }
}

__global__ void gate_kernel(const float* __restrict__ x,
                            const float* __restrict__ gw) {
    int warp = (blockIdx.x * blockDim.x + threadIdx.x) >> 5;
    int lane = threadIdx.x & 31;
    if (warp >= TOK) return;
    const float* xr = x + (size_t)warp * HDIM;
    float acc[NEXP];
#pragma unroll
    for (int e = 0; e < NEXP; e++) acc[e] = 0.f;
    for (int h = lane; h < HDIM; h += 32) {
        float xv = xr[h];
        const float* g = gw + (size_t)h * NEXP;
#pragma unroll
        for (int e = 0; e < NEXP; e++) acc[e] = fmaf(xv, g[e], acc[e]);
    }
#pragma unroll
    for (int e = 0; e < NEXP; e++) {
#pragma unroll
        for (int off = 16; off > 0; off >>= 1)
            acc[e] += __shfl_xor_sync(0xffffffffu, acc[e], off);
    }
    if (lane == 0) {
        int e0 = 0; float v0 = acc[0];
#pragma unroll
        for (int e = 1; e < NEXP; e++) if (acc[e] > v0) { v0 = acc[e]; e0 = e; }
        int e1 = -1; float v1 = -1e30f;
#pragma unroll
        for (int e = 0; e < NEXP; e++)
            if (e != e0 && acc[e] > v1) { v1 = acc[e]; e1 = e; }
        float p1 = expf(v1 - v0);
        float s  = 1.f + p1;
        int t = warp;
        g_tope[2*t]   = e0;  g_topw[2*t]   = 1.f / s;
        g_tope[2*t+1] = e1;  g_topw[2*t+1] = p1 / s;
        atomicAdd(&g_counts[e0], 1);
        atomicAdd(&g_counts[e1], 1);
    }
}

__global__ void scan_kernel() {
    int s = 0;
    for (int e = 0; e < NEXP; e++) {
        g_offset[e] = s;
        s += g_counts[e];
        g_cursor[e] = 0;
    }
}

__global__ void fill_kernel() {
    int t = blockIdx.x * blockDim.x + threadIdx.x;
    if (t >= TOK) return;
#pragma unroll
    for (int k = 0; k < 2; k++) {
        int e = g_tope[2*t + k];
        int slot = g_offset[e] + atomicAdd(&g_cursor[e], 1);
        g_rows[slot] = t;
        g_dest[slot] = 2*t + k;
        g_wgt[slot]  = g_topw[2*t + k];
    }
}

// ======= GEMM1 (mma.sync bf16 hi/lo): h = silu(X@w1)*(X@w3) ======================
// CTA: M=128 x 64 I-cols, 256 threads (8 warps: wm=wid>>1 M-slice, wn=wid&1 N-slice).
// B tile: rows 0-63 = w1 cols, 64-127 = w3 cols. K-chunk 32. Static smem 40KB.
// Epilogue writes h pre-split (bf16 hi/lo planes).
__global__ void __launch_bounds__(256) gemm1_kernel(const float* __restrict__ x,
                                                    const float* __restrict__ w1,
                                                    const float* __restrict__ w3) {
    __shared__ __align__(16) uint8_t Ah[128*80], Al[128*80], Bh[128*80], Bl[128*80];
    int e = blockIdx.z;
    int count = g_counts[e];
    int mbase = blockIdx.y * 128;
    if (mbase >= count) return;
    int off  = g_offset[e];
    int nb64 = blockIdx.x * 64;
    int tid = threadIdx.x, lane = tid & 31, wid = tid >> 5;
    int wm = wid >> 1, wn = wid & 1;

    uint32_t ah_b = smem_u32(Ah), al_b = smem_u32(Al);
    uint32_t bh_b = smem_u32(Bh), bl_b = smem_u32(Bl);

    // A rows: thread covers rows (tid>>3)+32j (j<4), float4 slot aq
    int tokr[4];
#pragma unroll
    for (int j = 0; j < 4; j++) {
        int rr = mbase + (tid >> 3) + 32 * j;
        if (rr >= count) rr = count - 1;
        tokr[j] = g_rows[off + rr];
    }
    int aq = tid & 7;

    // B: thread covers k-rows k2,k2+1 and n-cols n4..n4+3 of each matrix
    int k2 = (tid >> 4) * 2;       // 0..30
    int n4 = (tid & 15) * 4;       // 0..60
    const float* w1p = w1 + (size_t)e * HDIM * IDIM + nb64 + n4;
    const float* w3p = w3 + (size_t)e * HDIM * IDIM + nb64 + n4;

    float zacc[2][4][4], uacc[2][4][4];
#pragma unroll
    for (int m = 0; m < 2; m++)
#pragma unroll
        for (int i = 0; i < 4; i++)
#pragma unroll
            for (int j = 0; j < 4; j++) { zacc[m][i][j] = 0.f; uacc[m][i][j] = 0.f; }

    for (int ch = 0; ch < HDIM / 32; ch++) {
        int kb = ch * 32;
        // ---- A: gather fp32, split hi/lo ----
#pragma unroll
        for (int j = 0; j < 4; j++) {
            int r = (tid >> 3) + 32 * j;
            float4 f = *(const float4*)(x + (size_t)tokr[j] * HDIM + kb + aq * 4);
            __nv_bfloat16 h0,h1,h2,h3,l0,l1,l2,l3;
            split32(f.x,h0,l0); split32(f.y,h1,l1);
            split32(f.z,h2,l2); split32(f.w,h3,l3);
            uint2 vh = { pack2(h0,h1), pack2(h2,h3) };
            uint2 vl = { pack2(l0,l1), pack2(l2,l3) };
            uint32_t o = (uint32_t)(r * 80 + (aq >> 1) * 16 + (aq & 1) * 8);
            *(uint2*)(Ah + o) = vh;
            *(uint2*)(Al + o) = vl;
        }
        // ---- B: fp32 rows (n-contiguous), transpose+split ----
        {
            const float* r0 = w1p + (size_t)(kb + k2) * IDIM;
            float4 f0 = *(const float4*)r0;
            float4 f1 = *(const float4*)(r0 + IDIM);
            float a0[4] = { f0.x, f0.y, f0.z, f0.w };
            float a1[4] = { f1.x, f1.y, f1.z, f1.w };
#pragma unroll
            for (int j = 0; j < 4; j++) {
                __nv_bfloat16 h0,l0,h1,l1;
                split32(a0[j], h0, l0); split32(a1[j], h1, l1);
                uint32_t o = (uint32_t)((n4 + j) * 80 + k2 * 2);
                *(uint32_t*)(Bh + o) = pack2(h0, h1);
                *(uint32_t*)(Bl + o) = pack2(l0, l1);
            }
            const float* r3 = w3p + (size_t)(kb + k2) * IDIM;
            float4 g0 = *(const float4*)r3;
            float4 g1 = *(const float4*)(r3 + IDIM);
            float b0[4] = { g0.x, g0.y, g0.z, g0.w };
            float b1[4] = { g1.x, g1.y, g1.z, g1.w };
#pragma unroll
            for (int j = 0; j < 4; j++) {
                __nv_bfloat16 h0,l0,h1,l1;
                split32(b0[j], h0, l0); split32(b1[j], h1, l1);
                uint32_t o = (uint32_t)((64 + n4 + j) * 80 + k2 * 2);
                *(uint32_t*)(Bh + o) = pack2(h0, h1);
                *(uint32_t*)(Bl + o) = pack2(l0, l1);
            }
        }
        __syncthreads();
        // ---- compute: 2 x k16 steps ----
#pragma unroll
        for (int ks = 0; ks < 2; ks++) {
            int lrow = lane & 15;
            int lk   = ks * 2 + (lane >> 4);
            uint32_t a_h[2][4], a_l[2][4];
#pragma unroll
            for (int mf = 0; mf < 2; mf++) {
                uint32_t aoff = (uint32_t)((wm * 32 + mf * 16 + lrow) * 80 + lk * 16);
                ldm4(ah_b + aoff, a_h[mf]);
                ldm4(al_b + aoff, a_l[mf]);
            }
            int nrow = (lane & 7) + ((lane >> 4) << 3);
            int ck   = ks * 2 + ((lane >> 3) & 1);
#pragma unroll
            for (int g = 0; g < 2; g++) {
#pragma unroll
                for (int b16 = 0; b16 < 2; b16++) {
                    uint32_t boff = (uint32_t)((g * 64 + wn * 32 + b16 * 16 + nrow) * 80 + ck * 16);
                    uint32_t b_h[4], b_l[4];
                    ldm4(bh_b + boff, b_h);
                    ldm4(bl_b + boff, b_l);
#pragma unroll
                    for (int mf = 0; mf < 2; mf++) {
#pragma unroll
                        for (int s = 0; s < 2; s++) {
                            float* cc = g ? uacc[mf][b16 * 2 + s] : zacc[mf][b16 * 2 + s];
                            mma_bf16(cc, a_h[mf], b_h[2*s], b_h[2*s+1]);
                            mma_bf16(cc, a_h[mf], b_l[2*s], b_l[2*s+1]);
                            mma_bf16(cc, a_l[mf], b_h[2*s], b_h[2*s+1]);
                        }
                    }
                }
            }
        }
        __syncthreads();
    }

    // ---- epilogue: silu(z)*u, split, write bf16 hi/lo planes ----
#pragma unroll
    for (int mf = 0; mf < 2; mf++) {
        int r0 = wm * 32 + mf * 16 + (lane >> 2);
#pragma unroll
        for (int half = 0; half < 2; half++) {
            int rr = mbase + r0 + half * 8;
            if (rr < count) {
                int colb = nb64 + wn * 32 + (lane & 3) * 2;
                size_t base = ((size_t)(off + rr) * IDIM + colb) >> 1;
#pragma unroll
                for (int nb8 = 0; nb8 < 4; nb8++) {
                    float z0 = zacc[mf][nb8][half * 2];
                    float z1 = zacc[mf][nb8][half * 2 + 1];
                    float u0 = uacc[mf][nb8][half * 2];
                    float u1 = uacc[mf][nb8][half * 2 + 1];
                    float h0 = z0 / (1.f + __expf(-z0)) * u0;
                    float h1 = z1 / (1.f + __expf(-z1)) * u1;
                    __nv_bfloat16 hh0, ll0, hh1, ll1;
                    split32(h0, hh0, ll0); split32(h1, hh1, ll1);
                    g_hbh[base + nb8 * 4] = pack2(hh0, hh1);
                    g_hbl[base + nb8 * 4] = pack2(ll0, ll1);
                }
            }
        }
    }
}

// ======= GEMM2 (mma.sync bf16 hi/lo, pre-split A): y = h @ w2 ====================
// CTA: M=128 slot-rows x 32 H-cols, 128 threads. A = copy from hi/lo planes.
__global__ void __launch_bounds__(128) gemm2_kernel(const float* __restrict__ w2) {
    __shared__ __align__(16) uint8_t Ah[128*80], Al[128*80], Bh[32*80], Bl[32*80];
    int e = blockIdx.z;
    int count = g_counts[e];
    int mbase = blockIdx.y * 128;
    if (mbase >= count) return;
    int off  = g_offset[e];
    int nb32 = blockIdx.x * 32;
    int tid = threadIdx.x, lane = tid & 31, wid = tid >> 5;

    uint32_t ah_b = smem_u32(Ah), al_b = smem_u32(Al);
    uint32_t bh_b = smem_u32(Bh), bl_b = smem_u32(Bl);

    const uint32_t* ah_src[8];
    const uint32_t* al_src[8];
#pragma unroll
    for (int j = 0; j < 8; j++) {
        int rr = mbase + (tid >> 3) + 16 * j;
        if (rr >= count) rr = count - 1;
        size_t b = (size_t)(off + rr) * (IDIM / 2);
        ah_src[j] = g_hbh + b;
        al_src[j] = g_hbl + b;
    }
    int aq = tid & 7;

    int k2 = (tid >> 3) * 2;       // 0..30
    int n4 = (tid & 7) * 4;        // 0..28
    const float* w2p = w2 + (size_t)e * IDIM * HDIM + nb32 + n4;

    float acc[2][4][4];
#pragma unroll
    for (int m = 0; m < 2; m++)
#pragma unroll
        for (int i = 0; i < 4; i++)
#pragma unroll
            for (int j = 0; j < 4; j++) acc[m][i][j] = 0.f;

    for (int ch = 0; ch < IDIM / 32; ch++) {
        int kb = ch * 32;
        // ---- A: pure copy of pre-split planes ----
#pragma unroll
        for (int j = 0; j < 8; j++) {
            int r = (tid >> 3) + 16 * j;
            uint2 vh = *(const uint2*)(ah_src[j] + (kb >> 1) + aq * 2);
            uint2 vl = *(const uint2*)(al_src[j] + (kb >> 1) + aq * 2);
            uint32_t o = (uint32_t)(r * 80 + (aq >> 1) * 16 + (aq & 1) * 8);
            *(uint2*)(Ah + o) = vh;
            *(uint2*)(Al + o) = vl;
        }
        // ---- B: w2 fp32 rows (N-contiguous), transpose+split ----
        {
            const float* r0 = w2p + (size_t)(kb + k2) * HDIM;
            float4 f0 = *(const float4*)r0;
            float4 f1 = *(const float4*)(r0 + HDIM);
            float a0[4] = { f0.x, f0.y, f0.z, f0.w };
            float a1[4] = { f1.x, f1.y, f1.z, f1.w };
#pragma unroll
            for (int j = 0; j < 4; j++) {
                __nv_bfloat16 h0,l0,h1,l1;
                split32(a0[j], h0, l0); split32(a1[j], h1, l1);
                uint32_t o = (uint32_t)((n4 + j) * 80 + k2 * 2);
                *(uint32_t*)(Bh + o) = pack2(h0, h1);
                *(uint32_t*)(Bl + o) = pack2(l0, l1);
            }
        }
        __syncthreads();
#pragma unroll
        for (int ks = 0; ks < 2; ks++) {
            int lrow = lane & 15;
            int lk   = ks * 2 + (lane >> 4);
            uint32_t a_h[2][4], a_l[2][4];
#pragma unroll
            for (int mf = 0; mf < 2; mf++) {
                uint32_t aoff = (uint32_t)((wid * 32 + mf * 16 + lrow) * 80 + lk * 16);
                ldm4(ah_b + aoff, a_h[mf]);
                ldm4(al_b + aoff, a_l[mf]);
            }
            int nrow = (lane & 7) + ((lane >> 4) << 3);
            int ck   = ks * 2 + ((lane >> 3) & 1);
#pragma unroll
            for (int b16 = 0; b16 < 2; b16++) {
                uint32_t boff = (uint32_t)((b16 * 16 + nrow) * 80 + ck * 16);
                uint32_t b_h[4], b_l[4];
                ldm4(bh_b + boff, b_h);
                ldm4(bl_b + boff, b_l);
#pragma unroll
                for (int mf = 0; mf < 2; mf++) {
#pragma unroll
                    for (int s = 0; s < 2; s++) {
                        float* cc = acc[mf][b16 * 2 + s];
                        mma_bf16(cc, a_h[mf], b_h[2*s], b_h[2*s+1]);
                        mma_bf16(cc, a_h[mf], b_l[2*s], b_l[2*s+1]);
                        mma_bf16(cc, a_l[mf], b_h[2*s], b_h[2*s+1]);
                    }
                }
            }
        }
        __syncthreads();
    }

    // ---- epilogue: weight-scale + scatter to ybuf[dest] ----
#pragma unroll
    for (int mf = 0; mf < 2; mf++) {
        int r0 = wid * 32 + mf * 16 + (lane >> 2);
#pragma unroll
        for (int half = 0; half < 2; half++) {
            int rr = mbase + r0 + half * 8;
            if (rr < count) {
                int slot = off + rr;
                float w = g_wgt[slot];
                int   d = g_dest[slot];
                float* dst = g_ybuf + (size_t)d * HDIM + nb32 + (lane & 3) * 2;
#pragma unroll
                for (int nb8 = 0; nb8 < 4; nb8++) {
                    float2 o;
                    o.x = w * acc[mf][nb8][half * 2];
                    o.y = w * acc[mf][nb8][half * 2 + 1];
                    *(float2*)(dst + nb8 * 8) = o;
                }
            }
        }
    }
}

// ---------------- combine ----------------
__global__ void combine_kernel(float* __restrict__ out) {
    const int W = HDIM / 4;
    int i = blockIdx.x * blockDim.x + threadIdx.x;
    if (i >= TOK * W) return;
    int t = i / W, col = i % W;
    const float4* y = (const float4*)g_ybuf;
    float4 a = y[(size_t)(2 * t) * W + col];
    float4 b = y[(size_t)(2 * t + 1) * W + col];
    float4 o = { a.x + b.x, a.y + b.y, a.z + b.z, a.w + b.w };
    ((float4*)out)[i] = o;
}

// ---------------- launch ----------------
extern "C" void kernel_launch(void* const* d_in, const int* in_sizes, int n_in,
                              void* d_out, int out_size) {
    const float* x  = (const float*)d_in[0];   // [T, H]
    const float* gw = (const float*)d_in[1];   // [H, E]
    const float* w1 = (const float*)d_in[2];   // [E, H, I]
    const float* w3 = (const float*)d_in[3];   // [E, H, I]
    const float* w2 = (const float*)d_in[4];   // [E, I, H]
    float* out = (float*)d_out;                // [T, H]

    init_kernel<<<1, 32>>>();
    gate_kernel<<<TOK / 8, 256>>>(x, gw);
    scan_kernel<<<1, 1>>>();
    fill_kernel<<<TOK / 256, 256>>>();

    dim3 g1(IDIM / 64, NASSIGN / 128, NEXP);
    gemm1_kernel<<<g1, 256>>>(x, w1, w3);

    dim3 g2(HDIM / 32, NASSIGN / 128, NEXP);
    gemm2_kernel<<<g2, 128>>>(w2);

    combine_kernel<<<(TOK * (HDIM / 4)) / 256, 256>>>(out);
}

// round 13
// speedup vs baseline: 1.2613x; 1.2613x over previous
#include <cuda_runtime.h>
#include <cuda_bf16.h>
#include <stdint.h>
#include <math.h>

// Problem shape (fixed by the dataset)
#define TOK 8192          // B*S tokens
#define HDIM 1024
#define NEXP 8
#define IDIM 4096
#define NASSIGN (TOK*2)

// ------------- device scratch (TOTAL 335 MB: the proven envelope) -------------
__device__ int   g_counts[NEXP];
__device__ int   g_cursor[NEXP];
__device__ int   g_offset[NEXP];
__device__ int   g_rows[NASSIGN];
__device__ int   g_dest[NASSIGN];
__device__ float g_wgt[NASSIGN];
__device__ int   g_tope[NASSIGN];
__device__ float g_topw[NASSIGN];
// h stored as bf16 hi/lo planes, packed 2 cols per uint32
__device__ uint32_t g_hbh[(size_t)NASSIGN * IDIM / 2];  // 134 MB
__device__ uint32_t g_hbl[(size_t)NASSIGN * IDIM / 2];  // 134 MB
__device__ float    g_ybuf[(size_t)NASSIGN * HDIM];     // 67 MB

// ---------------- helpers ----------------
__device__ __forceinline__ uint32_t smem_u32(const void* p) {
    uint32_t a;
    asm("{ .reg .u64 t; cvta.to.shared.u64 t, %1; cvt.u32.u64 %0, t; }" : "=r"(a) : "l"(p));
    return a;
}
__device__ __forceinline__ void ldm4(uint32_t addr, uint32_t* r) {
    asm volatile("ldmatrix.sync.aligned.m8n8.x4.shared.b16 {%0,%1,%2,%3}, [%4];\n"
        : "=r"(r[0]), "=r"(r[1]), "=r"(r[2]), "=r"(r[3]) : "r"(addr));
}
__device__ __forceinline__ void mma_bf16(float* c, const uint32_t* a, uint32_t b0, uint32_t b1) {
    asm volatile(
        "mma.sync.aligned.m16n8k16.row.col.f32.bf16.bf16.f32 "
        "{%0,%1,%2,%3}, {%4,%5,%6,%7}, {%8,%9}, {%0,%1,%2,%3};\n"
        : "+f"(c[0]), "+f"(c[1]), "+f"(c[2]), "+f"(c[3])
        : "r"(a[0]), "r"(a[1]), "r"(a[2]), "r"(a[3]), "r"(b0), "r"(b1));
}
__device__ __forceinline__ uint32_t pack2(__nv_bfloat16 a, __nv_bfloat16 b) {
    __nv_bfloat162 t = __halves2bfloat162(a, b);
    return *reinterpret_cast<uint32_t*>(&t);
}
__device__ __forceinline__ void split32(float f, __nv_bfloat16& h, __nv_bfloat16& l) {
    h = __float2bfloat16_rn(f);
    l = __float2bfloat16_rn(f - __bfloat162float(h));
}

// ---------------- routing kernels (proven) ----------------
__global__ void init_kernel() {
    int i = threadIdx.x;
    if (i < NEXP) { g_counts[i] = 0; g_cursor[i] = 0; }
}

__global__ void gate_kernel(const float* __restrict__ x,
                            const float* __restrict__ gw) {
    int warp = (blockIdx.x * blockDim.x + threadIdx.x) >> 5;
    int lane = threadIdx.x & 31;
    if (warp >= TOK) return;
    const float* xr = x + (size_t)warp * HDIM;
    float acc[NEXP];
#pragma unroll
    for (int e = 0; e < NEXP; e++) acc[e] = 0.f;
    for (int h = lane; h < HDIM; h += 32) {
        float xv = xr[h];
        const float* g = gw + (size_t)h * NEXP;
#pragma unroll
        for (int e = 0; e < NEXP; e++) acc[e] = fmaf(xv, g[e], acc[e]);
    }
#pragma unroll
    for (int e = 0; e < NEXP; e++) {
#pragma unroll
        for (int off = 16; off > 0; off >>= 1)
            acc[e] += __shfl_xor_sync(0xffffffffu, acc[e], off);
    }
    if (lane == 0) {
        int e0 = 0; float v0 = acc[0];
#pragma unroll
        for (int e = 1; e < NEXP; e++) if (acc[e] > v0) { v0 = acc[e]; e0 = e; }
        int e1 = -1; float v1 = -1e30f;
#pragma unroll
        for (int e = 0; e < NEXP; e++)
            if (e != e0 && acc[e] > v1) { v1 = acc[e]; e1 = e; }
        float p1 = expf(v1 - v0);
        float s  = 1.f + p1;
        int t = warp;
        g_tope[2*t]   = e0;  g_topw[2*t]   = 1.f / s;
        g_tope[2*t+1] = e1;  g_topw[2*t+1] = p1 / s;
        atomicAdd(&g_counts[e0], 1);
        atomicAdd(&g_counts[e1], 1);
    }
}

__global__ void scan_kernel() {
    int s = 0;
    for (int e = 0; e < NEXP; e++) {
        g_offset[e] = s;
        s += g_counts[e];
        g_cursor[e] = 0;
    }
}

__global__ void fill_kernel() {
    int t = blockIdx.x * blockDim.x + threadIdx.x;
    if (t >= TOK) return;
#pragma unroll
    for (int k = 0; k < 2; k++) {
        int e = g_tope[2*t + k];
        int slot = g_offset[e] + atomicAdd(&g_cursor[e], 1);
        g_rows[slot] = t;
        g_dest[slot] = 2*t + k;
        g_wgt[slot]  = g_topw[2*t + k];
    }
}

// ======= GEMM1 (ROUND-11 PROVEN mainloop): h = silu(X@w1)*(X@w3) =================
// CTA: M=128 rows x 32 I-cols, 128 threads. B tile 64 rows (0-31 w1, 32-63 w3).
// ONLY the epilogue differs from round 11: writes pre-split bf16 hi/lo planes.
__global__ void __launch_bounds__(128) gemm1_kernel(const float* __restrict__ x,
                                                    const float* __restrict__ w1,
                                                    const float* __restrict__ w3) {
    __shared__ __align__(16) uint8_t Ah[128*80], Al[128*80], Bh[64*80], Bl[64*80];
    int e = blockIdx.z;
    int count = g_counts[e];
    int mbase = blockIdx.y * 128;
    if (mbase >= count) return;
    int off  = g_offset[e];
    int nb32 = blockIdx.x * 32;
    int tid = threadIdx.x, lane = tid & 31, wid = tid >> 5;

    uint32_t ah_b = smem_u32(Ah), al_b = smem_u32(Al);
    uint32_t bh_b = smem_u32(Bh), bl_b = smem_u32(Bl);

    int tokr[8];
#pragma unroll
    for (int j = 0; j < 8; j++) {
        int rr = mbase + (tid >> 3) + 16 * j;
        if (rr >= count) rr = count - 1;
        tokr[j] = g_rows[off + rr];
    }
    int aq = tid & 7;

    int k2 = (tid >> 3) * 2;
    int n4 = (tid & 7) * 4;
    const float* w1p = w1 + (size_t)e * HDIM * IDIM + nb32 + n4;
    const float* w3p = w3 + (size_t)e * HDIM * IDIM + nb32 + n4;

    float zacc[2][4][4], uacc[2][4][4];
#pragma unroll
    for (int m = 0; m < 2; m++)
#pragma unroll
        for (int i = 0; i < 4; i++)
#pragma unroll
            for (int j = 0; j < 4; j++) { zacc[m][i][j] = 0.f; uacc[m][i][j] = 0.f; }

    for (int ch = 0; ch < HDIM / 32; ch++) {
        int kb = ch * 32;
#pragma unroll
        for (int j = 0; j < 8; j++) {
            int r = (tid >> 3) + 16 * j;
            float4 f = *(const float4*)(x + (size_t)tokr[j] * HDIM + kb + aq * 4);
            __nv_bfloat16 h0,h1,h2,h3,l0,l1,l2,l3;
            split32(f.x,h0,l0); split32(f.y,h1,l1);
            split32(f.z,h2,l2); split32(f.w,h3,l3);
            uint2 vh = { pack2(h0,h1), pack2(h2,h3) };
            uint2 vl = { pack2(l0,l1), pack2(l2,l3) };
            uint32_t o = (uint32_t)(r * 80 + (aq >> 1) * 16 + (aq & 1) * 8);
            *(uint2*)(Ah + o) = vh;
            *(uint2*)(Al + o) = vl;
        }
        {
            const float* r0 = w1p + (size_t)(kb + k2) * IDIM;
            float4 f0 = *(const float4*)r0;
            float4 f1 = *(const float4*)(r0 + IDIM);
            float a0[4] = { f0.x, f0.y, f0.z, f0.w };
            float a1[4] = { f1.x, f1.y, f1.z, f1.w };
#pragma unroll
            for (int j = 0; j < 4; j++) {
                __nv_bfloat16 h0,l0,h1,l1;
                split32(a0[j], h0, l0); split32(a1[j], h1, l1);
                uint32_t o = (uint32_t)((n4 + j) * 80 + k2 * 2);
                *(uint32_t*)(Bh + o) = pack2(h0, h1);
                *(uint32_t*)(Bl + o) = pack2(l0, l1);
            }
            const float* r3 = w3p + (size_t)(kb + k2) * IDIM;
            float4 g0 = *(const float4*)r3;
            float4 g1 = *(const float4*)(r3 + IDIM);
            float b0[4] = { g0.x, g0.y, g0.z, g0.w };
            float b1[4] = { g1.x, g1.y, g1.z, g1.w };
#pragma unroll
            for (int j = 0; j < 4; j++) {
                __nv_bfloat16 h0,l0,h1,l1;
                split32(b0[j], h0, l0); split32(b1[j], h1, l1);
                uint32_t o = (uint32_t)((32 + n4 + j) * 80 + k2 * 2);
                *(uint32_t*)(Bh + o) = pack2(h0, h1);
                *(uint32_t*)(Bl + o) = pack2(l0, l1);
            }
        }
        __syncthreads();
#pragma unroll
        for (int ks = 0; ks < 2; ks++) {
            int lrow = lane & 15;
            int lk   = ks * 2 + (lane >> 4);
            uint32_t a_h[2][4], a_l[2][4];
#pragma unroll
            for (int mf = 0; mf < 2; mf++) {
                uint32_t aoff = (uint32_t)((wid * 32 + mf * 16 + lrow) * 80 + lk * 16);
                ldm4(ah_b + aoff, a_h[mf]);
                ldm4(al_b + aoff, a_l[mf]);
            }
            int nrow = (lane & 7) + ((lane >> 4) << 3);
            int ck   = ks * 2 + ((lane >> 3) & 1);
#pragma unroll
            for (int g = 0; g < 2; g++) {
#pragma unroll
                for (int b16 = 0; b16 < 2; b16++) {
                    uint32_t boff = (uint32_t)((g * 32 + b16 * 16 + nrow) * 80 + ck * 16);
                    uint32_t b_h[4], b_l[4];
                    ldm4(bh_b + boff, b_h);
                    ldm4(bl_b + boff, b_l);
#pragma unroll
                    for (int mf = 0; mf < 2; mf++) {
#pragma unroll
                        for (int s = 0; s < 2; s++) {
                            float* cc = g ? uacc[mf][b16 * 2 + s] : zacc[mf][b16 * 2 + s];
                            mma_bf16(cc, a_h[mf], b_h[2*s], b_h[2*s+1]);
                            mma_bf16(cc, a_h[mf], b_l[2*s], b_l[2*s+1]);
                            mma_bf16(cc, a_l[mf], b_h[2*s], b_h[2*s+1]);
                        }
                    }
                }
            }
        }
        __syncthreads();
    }

    // ---- epilogue (the ONLY change vs round 11): write pre-split hi/lo planes ----
#pragma unroll
    for (int mf = 0; mf < 2; mf++) {
        int r0 = wid * 32 + mf * 16 + (lane >> 2);
#pragma unroll
        for (int half = 0; half < 2; half++) {
            int rr = mbase + r0 + half * 8;
            if (rr < count) {
                int colb = nb32 + (lane & 3) * 2;
                size_t base = ((size_t)(off + rr) * IDIM + colb) >> 1;
#pragma unroll
                for (int nb8 = 0; nb8 < 4; nb8++) {
                    float z0 = zacc[mf][nb8][half * 2];
                    float z1 = zacc[mf][nb8][half * 2 + 1];
                    float u0 = uacc[mf][nb8][half * 2];
                    float u1 = uacc[mf][nb8][half * 2 + 1];
                    float h0 = z0 / (1.f + __expf(-z0)) * u0;
                    float h1 = z1 / (1.f + __expf(-z1)) * u1;
                    __nv_bfloat16 hh0, ll0, hh1, ll1;
                    split32(h0, hh0, ll0); split32(h1, hh1, ll1);
                    g_hbh[base + nb8 * 4] = pack2(hh0, hh1);
                    g_hbl[base + nb8 * 4] = pack2(ll0, ll1);
                }
            }
        }
    }
}

// ======= GEMM2 (round-12 version: pre-split A copy): y = h @ w2 ==================
__global__ void __launch_bounds__(128) gemm2_kernel(const float* __restrict__ w2) {
    __shared__ __align__(16) uint8_t Ah[128*80], Al[128*80], Bh[32*80], Bl[32*80];
    int e = blockIdx.z;
    int count = g_counts[e];
    int mbase = blockIdx.y * 128;
    if (mbase >= count) return;
    int off  = g_offset[e];
    int nb32 = blockIdx.x * 32;
    int tid = threadIdx.x, lane = tid & 31, wid = tid >> 5;

    uint32_t ah_b = smem_u32(Ah), al_b = smem_u32(Al);
    uint32_t bh_b = smem_u32(Bh), bl_b = smem_u32(Bl);

    const uint32_t* ah_src[8];
    const uint32_t* al_src[8];
#pragma unroll
    for (int j = 0; j < 8; j++) {
        int rr = mbase + (tid >> 3) + 16 * j;
        if (rr >= count) rr = count - 1;
        size_t b = (size_t)(off + rr) * (IDIM / 2);
        ah_src[j] = g_hbh + b;
        al_src[j] = g_hbl + b;
    }
    int aq = tid & 7;

    int k2 = (tid >> 3) * 2;
    int n4 = (tid & 7) * 4;
    const float* w2p = w2 + (size_t)e * IDIM * HDIM + nb32 + n4;

    float acc[2][4][4];
#pragma unroll
    for (int m = 0; m < 2; m++)
#pragma unroll
        for (int i = 0; i < 4; i++)
#pragma unroll
            for (int j = 0; j < 4; j++) acc[m][i][j] = 0.f;

    for (int ch = 0; ch < IDIM / 32; ch++) {
        int kb = ch * 32;
#pragma unroll
        for (int j = 0; j < 8; j++) {
            int r = (tid >> 3) + 16 * j;
            uint2 vh = *(const uint2*)(ah_src[j] + (kb >> 1) + aq * 2);
            uint2 vl = *(const uint2*)(al_src[j] + (kb >> 1) + aq * 2);
            uint32_t o = (uint32_t)(r * 80 + (aq >> 1) * 16 + (aq & 1) * 8);
            *(uint2*)(Ah + o) = vh;
            *(uint2*)(Al + o) = vl;
        }
        {
            const float* r0 = w2p + (size_t)(kb + k2) * HDIM;
            float4 f0 = *(const float4*)r0;
            float4 f1 = *(const float4*)(r0 + HDIM);
            float a0[4] = { f0.x, f0.y, f0.z, f0.w };
            float a1[4] = { f1.x, f1.y, f1.z, f1.w };
#pragma unroll
            for (int j = 0; j < 4; j++) {
                __nv_bfloat16 h0,l0,h1,l1;
                split32(a0[j], h0, l0); split32(a1[j], h1, l1);
                uint32_t o = (uint32_t)((n4 + j) * 80 + k2 * 2);
                *(uint32_t*)(Bh + o) = pack2(h0, h1);
                *(uint32_t*)(Bl + o) = pack2(l0, l1);
            }
        }
        __syncthreads();
#pragma unroll
        for (int ks = 0; ks < 2; ks++) {
            int lrow = lane & 15;
            int lk   = ks * 2 + (lane >> 4);
            uint32_t a_h[2][4], a_l[2][4];
#pragma unroll
            for (int mf = 0; mf < 2; mf++) {
                uint32_t aoff = (uint32_t)((wid * 32 + mf * 16 + lrow) * 80 + lk * 16);
                ldm4(ah_b + aoff, a_h[mf]);
                ldm4(al_b + aoff, a_l[mf]);
            }
            int nrow = (lane & 7) + ((lane >> 4) << 3);
            int ck   = ks * 2 + ((lane >> 3) & 1);
#pragma unroll
            for (int b16 = 0; b16 < 2; b16++) {
                uint32_t boff = (uint32_t)((b16 * 16 + nrow) * 80 + ck * 16);
                uint32_t b_h[4], b_l[4];
                ldm4(bh_b + boff, b_h);
                ldm4(bl_b + boff, b_l);
#pragma unroll
                for (int mf = 0; mf < 2; mf++) {
#pragma unroll
                    for (int s = 0; s < 2; s++) {
                        float* cc = acc[mf][b16 * 2 + s];
                        mma_bf16(cc, a_h[mf], b_h[2*s], b_h[2*s+1]);
                        mma_bf16(cc, a_h[mf], b_l[2*s], b_l[2*s+1]);
                        mma_bf16(cc, a_l[mf], b_h[2*s], b_h[2*s+1]);
                    }
                }
            }
        }
        __syncthreads();
    }

#pragma unroll
    for (int mf = 0; mf < 2; mf++) {
        int r0 = wid * 32 + mf * 16 + (lane >> 2);
#pragma unroll
        for (int half = 0; half < 2; half++) {
            int rr = mbase + r0 + half * 8;
            if (rr < count) {
                int slot = off + rr;
                float w = g_wgt[slot];
                int   d = g_dest[slot];
                float* dst = g_ybuf + (size_t)d * HDIM + nb32 + (lane & 3) * 2;
#pragma unroll
                for (int nb8 = 0; nb8 < 4; nb8++) {
                    float2 o;
                    o.x = w * acc[mf][nb8][half * 2];
                    o.y = w * acc[mf][nb8][half * 2 + 1];
                    *(float2*)(dst + nb8 * 8) = o;
                }
            }
        }
    }
}

// ---------------- combine ----------------
__global__ void combine_kernel(float* __restrict__ out) {
    const int W = HDIM / 4;
    int i = blockIdx.x * blockDim.x + threadIdx.x;
    if (i >= TOK * W) return;
    int t = i / W, col = i % W;
    const float4* y = (const float4*)g_ybuf;
    float4 a = y[(size_t)(2 * t) * W + col];
    float4 b = y[(size_t)(2 * t + 1) * W + col];
    float4 o = { a.x + b.x, a.y + b.y, a.z + b.z, a.w + b.w };
    ((float4*)out)[i] = o;
}

// ---------------- launch ----------------
extern "C" void kernel_launch(void* const* d_in, const int* in_sizes, int n_in,
                              void* d_out, int out_size) {
    const float* x  = (const float*)d_in[0];   // [T, H]
    const float* gw = (const float*)d_in[1];   // [H, E]
    const float* w1 = (const float*)d_in[2];   // [E, H, I]
    const float* w3 = (const float*)d_in[3];   // [E, H, I]
    const float* w2 = (const float*)d_in[4];   // [E, I, H]
    float* out = (float*)d_out;                // [T, H]

    init_kernel<<<1, 32>>>();
    gate_kernel<<<TOK / 8, 256>>>(x, gw);
    scan_kernel<<<1, 1>>>();
    fill_kernel<<<TOK / 256, 256>>>();

    dim3 g1(IDIM / 32, NASSIGN / 128, NEXP);
    gemm1_kernel<<<g1, 128>>>(x, w1, w3);

    dim3 g2(HDIM / 32, NASSIGN / 128, NEXP);
    gemm2_kernel<<<g2, 128>>>(w2);

    combine_kernel<<<(TOK * (HDIM / 4)) / 256, 256>>>(out);
}

// round 14
// speedup vs baseline: 1.3158x; 1.0432x over previous
#include <cuda_runtime.h>
#include <cuda_bf16.h>
#include <stdint.h>
#include <math.h>

// Problem shape (fixed by the dataset)
#define TOK 8192          // B*S tokens
#define HDIM 1024
#define NEXP 8
#define IDIM 4096
#define NASSIGN (TOK*2)

// ------------- device scratch (367 MB total; known-bad point is 590 MB) -------------
__device__ int   g_counts[NEXP];
__device__ int   g_cursor[NEXP];
__device__ int   g_offset[NEXP];
__device__ int   g_rows[NASSIGN];
__device__ int   g_dest[NASSIGN];
__device__ float g_wgt[NASSIGN];
__device__ int   g_tope[NASSIGN];
__device__ float g_topw[NASSIGN];
// X pre-split to bf16 hi/lo planes, per token, 2 cols packed per uint32 (16 MB each)
__device__ uint32_t g_xh[(size_t)TOK * HDIM / 2];
__device__ uint32_t g_xl[(size_t)TOK * HDIM / 2];
__device__ float g_hbuf[(size_t)NASSIGN * IDIM];  // 268 MB (fp32, round-11 proven)
__device__ float g_ybuf[(size_t)NASSIGN * HDIM];  // 67 MB

// ---------------- helpers ----------------
__device__ __forceinline__ uint32_t smem_u32(const void* p) {
    uint32_t a;
    asm("{ .reg .u64 t; cvta.to.shared.u64 t, %1; cvt.u32.u64 %0, t; }" : "=r"(a) : "l"(p));
    return a;
}
__device__ __forceinline__ void ldm4(uint32_t addr, uint32_t* r) {
    asm volatile("ldmatrix.sync.aligned.m8n8.x4.shared.b16 {%0,%1,%2,%3}, [%4];\n"
        : "=r"(r[0]), "=r"(r[1]), "=r"(r[2]), "=r"(r[3]) : "r"(addr));
}
__device__ __forceinline__ void mma_bf16(float* c, const uint32_t* a, uint32_t b0, uint32_t b1) {
    asm volatile(
        "mma.sync.aligned.m16n8k16.row.col.f32.bf16.bf16.f32 "
        "{%0,%1,%2,%3}, {%4,%5,%6,%7}, {%8,%9}, {%0,%1,%2,%3};\n"
        : "+f"(c[0]), "+f"(c[1]), "+f"(c[2]), "+f"(c[3])
        : "r"(a[0]), "r"(a[1]), "r"(a[2]), "r"(a[3]), "r"(b0), "r"(b1));
}
__device__ __forceinline__ uint32_t pack2(__nv_bfloat16 a, __nv_bfloat16 b) {
    __nv_bfloat162 t = __halves2bfloat162(a, b);
    return *reinterpret_cast<uint32_t*>(&t);
}
__device__ __forceinline__ void split32(float f, __nv_bfloat16& h, __nv_bfloat16& l) {
    h = __float2bfloat16_rn(f);
    l = __float2bfloat16_rn(f - __bfloat162float(h));
}

// ---------------- routing kernels (proven) ----------------
__global__ void init_kernel() {
    int i = threadIdx.x;
    if (i < NEXP) { g_counts[i] = 0; g_cursor[i] = 0; }
}

__global__ void gate_kernel(const float* __restrict__ x,
                            const float* __restrict__ gw) {
    int warp = (blockIdx.x * blockDim.x + threadIdx.x) >> 5;
    int lane = threadIdx.x & 31;
    if (warp >= TOK) return;
    const float* xr = x + (size_t)warp * HDIM;
    float acc[NEXP];
#pragma unroll
    for (int e = 0; e < NEXP; e++) acc[e] = 0.f;
    for (int h = lane; h < HDIM; h += 32) {
        float xv = xr[h];
        const float* g = gw + (size_t)h * NEXP;
#pragma unroll
        for (int e = 0; e < NEXP; e++) acc[e] = fmaf(xv, g[e], acc[e]);
    }
#pragma unroll
    for (int e = 0; e < NEXP; e++) {
#pragma unroll
        for (int off = 16; off > 0; off >>= 1)
            acc[e] += __shfl_xor_sync(0xffffffffu, acc[e], off);
    }
    if (lane == 0) {
        int e0 = 0; float v0 = acc[0];
#pragma unroll
        for (int e = 1; e < NEXP; e++) if (acc[e] > v0) { v0 = acc[e]; e0 = e; }
        int e1 = -1; float v1 = -1e30f;
#pragma unroll
        for (int e = 0; e < NEXP; e++)
            if (e != e0 && acc[e] > v1) { v1 = acc[e]; e1 = e; }
        float p1 = expf(v1 - v0);
        float s  = 1.f + p1;
        int t = warp;
        g_tope[2*t]   = e0;  g_topw[2*t]   = 1.f / s;
        g_tope[2*t+1] = e1;  g_topw[2*t+1] = p1 / s;
        atomicAdd(&g_counts[e0], 1);
        atomicAdd(&g_counts[e1], 1);
    }
}

__global__ void scan_kernel() {
    int s = 0;
    for (int e = 0; e < NEXP; e++) {
        g_offset[e] = s;
        s += g_counts[e];
        g_cursor[e] = 0;
    }
}

__global__ void fill_kernel() {
    int t = blockIdx.x * blockDim.x + threadIdx.x;
    if (t >= TOK) return;
#pragma unroll
    for (int k = 0; k < 2; k++) {
        int e = g_tope[2*t + k];
        int slot = g_offset[e] + atomicAdd(&g_cursor[e], 1);
        g_rows[slot] = t;
        g_dest[slot] = 2*t + k;
        g_wgt[slot]  = g_topw[2*t + k];
    }
}

// ---------------- split X once per token into bf16 hi/lo planes ----------------
__global__ void __launch_bounds__(128) split_x_kernel(const float* __restrict__ x) {
    int tok = blockIdx.x;
    int t = threadIdx.x;
    const float4* src = (const float4*)(x + (size_t)tok * HDIM);
    uint2* dh = (uint2*)(g_xh + (size_t)tok * (HDIM / 2));
    uint2* dl = (uint2*)(g_xl + (size_t)tok * (HDIM / 2));
#pragma unroll
    for (int i = t; i < HDIM / 4; i += 128) {
        float4 f = src[i];
        __nv_bfloat16 h0,h1,h2,h3,l0,l1,l2,l3;
        split32(f.x,h0,l0); split32(f.y,h1,l1);
        split32(f.z,h2,l2); split32(f.w,h3,l3);
        dh[i] = make_uint2(pack2(h0,h1), pack2(h2,h3));
        dl[i] = make_uint2(pack2(l0,l1), pack2(l2,l3));
    }
}

// ======= GEMM1 (round-11 mainloop; A-path = copy of pre-split planes) ============
// CTA: M=128 rows x 32 I-cols, 128 threads. B tile 64 rows (0-31 w1, 32-63 w3).
__global__ void __launch_bounds__(128) gemm1_kernel(const float* __restrict__ w1,
                                                    const float* __restrict__ w3) {
    __shared__ __align__(16) uint8_t Ah[128*80], Al[128*80], Bh[64*80], Bl[64*80];
    int e = blockIdx.z;
    int count = g_counts[e];
    int mbase = blockIdx.y * 128;
    if (mbase >= count) return;
    int off  = g_offset[e];
    int nb32 = blockIdx.x * 32;
    int tid = threadIdx.x, lane = tid & 31, wid = tid >> 5;

    uint32_t ah_b = smem_u32(Ah), al_b = smem_u32(Al);
    uint32_t bh_b = smem_u32(Bh), bl_b = smem_u32(Bl);

    // A source row pointers (pre-split planes, gathered by token)
    const uint32_t* ah_src[8];
    const uint32_t* al_src[8];
#pragma unroll
    for (int j = 0; j < 8; j++) {
        int rr = mbase + (tid >> 3) + 16 * j;
        if (rr >= count) rr = count - 1;
        size_t b = (size_t)g_rows[off + rr] * (HDIM / 2);
        ah_src[j] = g_xh + b;
        al_src[j] = g_xl + b;
    }
    int aq = tid & 7;

    int k2 = (tid >> 3) * 2;
    int n4 = (tid & 7) * 4;
    const float* w1p = w1 + (size_t)e * HDIM * IDIM + nb32 + n4;
    const float* w3p = w3 + (size_t)e * HDIM * IDIM + nb32 + n4;

    float zacc[2][4][4], uacc[2][4][4];
#pragma unroll
    for (int m = 0; m < 2; m++)
#pragma unroll
        for (int i = 0; i < 4; i++)
#pragma unroll
            for (int j = 0; j < 4; j++) { zacc[m][i][j] = 0.f; uacc[m][i][j] = 0.f; }

    for (int ch = 0; ch < HDIM / 32; ch++) {
        int kb = ch * 32;
        // ---- A: pure copy of pre-split planes ----
#pragma unroll
        for (int j = 0; j < 8; j++) {
            int r = (tid >> 3) + 16 * j;
            uint2 vh = *(const uint2*)(ah_src[j] + (kb >> 1) + aq * 2);
            uint2 vl = *(const uint2*)(al_src[j] + (kb >> 1) + aq * 2);
            uint32_t o = (uint32_t)(r * 80 + (aq >> 1) * 16 + (aq & 1) * 8);
            *(uint2*)(Ah + o) = vh;
            *(uint2*)(Al + o) = vl;
        }
        // ---- B: fp32 rows (n-contiguous), transpose+split (round-11 pattern) ----
        {
            const float* r0 = w1p + (size_t)(kb + k2) * IDIM;
            float4 f0 = *(const float4*)r0;
            float4 f1 = *(const float4*)(r0 + IDIM);
            float a0[4] = { f0.x, f0.y, f0.z, f0.w };
            float a1[4] = { f1.x, f1.y, f1.z, f1.w };
#pragma unroll
            for (int j = 0; j < 4; j++) {
                __nv_bfloat16 h0,l0,h1,l1;
                split32(a0[j], h0, l0); split32(a1[j], h1, l1);
                uint32_t o = (uint32_t)((n4 + j) * 80 + k2 * 2);
                *(uint32_t*)(Bh + o) = pack2(h0, h1);
                *(uint32_t*)(Bl + o) = pack2(l0, l1);
            }
            const float* r3 = w3p + (size_t)(kb + k2) * IDIM;
            float4 g0 = *(const float4*)r3;
            float4 g1 = *(const float4*)(r3 + IDIM);
            float b0[4] = { g0.x, g0.y, g0.z, g0.w };
            float b1[4] = { g1.x, g1.y, g1.z, g1.w };
#pragma unroll
            for (int j = 0; j < 4; j++) {
                __nv_bfloat16 h0,l0,h1,l1;
                split32(b0[j], h0, l0); split32(b1[j], h1, l1);
                uint32_t o = (uint32_t)((32 + n4 + j) * 80 + k2 * 2);
                *(uint32_t*)(Bh + o) = pack2(h0, h1);
                *(uint32_t*)(Bl + o) = pack2(l0, l1);
            }
        }
        __syncthreads();
#pragma unroll
        for (int ks = 0; ks < 2; ks++) {
            int lrow = lane & 15;
            int lk   = ks * 2 + (lane >> 4);
            uint32_t a_h[2][4], a_l[2][4];
#pragma unroll
            for (int mf = 0; mf < 2; mf++) {
                uint32_t aoff = (uint32_t)((wid * 32 + mf * 16 + lrow) * 80 + lk * 16);
                ldm4(ah_b + aoff, a_h[mf]);
                ldm4(al_b + aoff, a_l[mf]);
            }
            int nrow = (lane & 7) + ((lane >> 4) << 3);
            int ck   = ks * 2 + ((lane >> 3) & 1);
#pragma unroll
            for (int g = 0; g < 2; g++) {
#pragma unroll
                for (int b16 = 0; b16 < 2; b16++) {
                    uint32_t boff = (uint32_t)((g * 32 + b16 * 16 + nrow) * 80 + ck * 16);
                    uint32_t b_h[4], b_l[4];
                    ldm4(bh_b + boff, b_h);
                    ldm4(bl_b + boff, b_l);
#pragma unroll
                    for (int mf = 0; mf < 2; mf++) {
#pragma unroll
                        for (int s = 0; s < 2; s++) {
                            float* cc = g ? uacc[mf][b16 * 2 + s] : zacc[mf][b16 * 2 + s];
                            mma_bf16(cc, a_h[mf], b_h[2*s], b_h[2*s+1]);
                            mma_bf16(cc, a_h[mf], b_l[2*s], b_l[2*s+1]);
                            mma_bf16(cc, a_l[mf], b_h[2*s], b_h[2*s+1]);
                        }
                    }
                }
            }
        }
        __syncthreads();
    }

    // ---- epilogue (round-11): silu(z)*u, fp32 float2 stores ----
#pragma unroll
    for (int mf = 0; mf < 2; mf++) {
        int r0 = wid * 32 + mf * 16 + (lane >> 2);
#pragma unroll
        for (int half = 0; half < 2; half++) {
            int rr = mbase + r0 + half * 8;
            if (rr < count) {
                float* dst = g_hbuf + (size_t)(off + rr) * IDIM + nb32 + (lane & 3) * 2;
#pragma unroll
                for (int nb8 = 0; nb8 < 4; nb8++) {
                    float z0 = zacc[mf][nb8][half * 2];
                    float z1 = zacc[mf][nb8][half * 2 + 1];
                    float u0 = uacc[mf][nb8][half * 2];
                    float u1 = uacc[mf][nb8][half * 2 + 1];
                    float2 h;
                    h.x = z0 / (1.f + __expf(-z0)) * u0;
                    h.y = z1 / (1.f + __expf(-z1)) * u1;
                    *(float2*)(dst + nb8 * 8) = h;
                }
            }
        }
    }
}

// ======= GEMM2 (round-11 proven): y = h @ w2, fp32 A split on the fly ============
__global__ void __launch_bounds__(128) gemm2_kernel(const float* __restrict__ w2) {
    __shared__ __align__(16) uint8_t Ah[128*80], Al[128*80], Bh[32*80], Bl[32*80];
    int e = blockIdx.z;
    int count = g_counts[e];
    int mbase = blockIdx.y * 128;
    if (mbase >= count) return;
    int off  = g_offset[e];
    int nb32 = blockIdx.x * 32;
    int tid = threadIdx.x, lane = tid & 31, wid = tid >> 5;

    uint32_t ah_b = smem_u32(Ah), al_b = smem_u32(Al);
    uint32_t bh_b = smem_u32(Bh), bl_b = smem_u32(Bl);

    const float* arows[8];
#pragma unroll
    for (int j = 0; j < 8; j++) {
        int rr = mbase + (tid >> 3) + 16 * j;
        if (rr >= count) rr = count - 1;
        arows[j] = g_hbuf + (size_t)(off + rr) * IDIM;
    }
    int aq = tid & 7;

    int k2 = (tid >> 3) * 2;
    int n4 = (tid & 7) * 4;
    const float* w2p = w2 + (size_t)e * IDIM * HDIM + nb32 + n4;

    float acc[2][4][4];
#pragma unroll
    for (int m = 0; m < 2; m++)
#pragma unroll
        for (int i = 0; i < 4; i++)
#pragma unroll
            for (int j = 0; j < 4; j++) acc[m][i][j] = 0.f;

    for (int ch = 0; ch < IDIM / 32; ch++) {
        int kb = ch * 32;
#pragma unroll
        for (int j = 0; j < 8; j++) {
            int r = (tid >> 3) + 16 * j;
            float4 f = *(const float4*)(arows[j] + kb + aq * 4);
            __nv_bfloat16 h0,h1,h2,h3,l0,l1,l2,l3;
            split32(f.x,h0,l0); split32(f.y,h1,l1);
            split32(f.z,h2,l2); split32(f.w,h3,l3);
            uint2 vh = { pack2(h0,h1), pack2(h2,h3) };
            uint2 vl = { pack2(l0,l1), pack2(l2,l3) };
            uint32_t o = (uint32_t)(r * 80 + (aq >> 1) * 16 + (aq & 1) * 8);
            *(uint2*)(Ah + o) = vh;
            *(uint2*)(Al + o) = vl;
        }
        {
            const float* r0 = w2p + (size_t)(kb + k2) * HDIM;
            float4 f0 = *(const float4*)r0;
            float4 f1 = *(const float4*)(r0 + HDIM);
            float a0[4] = { f0.x, f0.y, f0.z, f0.w };
            float a1[4] = { f1.x, f1.y, f1.z, f1.w };
#pragma unroll
            for (int j = 0; j < 4; j++) {
                __nv_bfloat16 h0,l0,h1,l1;
                split32(a0[j], h0, l0); split32(a1[j], h1, l1);
                uint32_t o = (uint32_t)((n4 + j) * 80 + k2 * 2);
                *(uint32_t*)(Bh + o) = pack2(h0, h1);
                *(uint32_t*)(Bl + o) = pack2(l0, l1);
            }
        }
        __syncthreads();
#pragma unroll
        for (int ks = 0; ks < 2; ks++) {
            int lrow = lane & 15;
            int lk   = ks * 2 + (lane >> 4);
            uint32_t a_h[2][4], a_l[2][4];
#pragma unroll
            for (int mf = 0; mf < 2; mf++) {
                uint32_t aoff = (uint32_t)((wid * 32 + mf * 16 + lrow) * 80 + lk * 16);
                ldm4(ah_b + aoff, a_h[mf]);
                ldm4(al_b + aoff, a_l[mf]);
            }
            int nrow = (lane & 7) + ((lane >> 4) << 3);
            int ck   = ks * 2 + ((lane >> 3) & 1);
#pragma unroll
            for (int b16 = 0; b16 < 2; b16++) {
                uint32_t boff = (uint32_t)((b16 * 16 + nrow) * 80 + ck * 16);
                uint32_t b_h[4], b_l[4];
                ldm4(bh_b + boff, b_h);
                ldm4(bl_b + boff, b_l);
#pragma unroll
                for (int mf = 0; mf < 2; mf++) {
#pragma unroll
                    for (int s = 0; s < 2; s++) {
                        float* cc = acc[mf][b16 * 2 + s];
                        mma_bf16(cc, a_h[mf], b_h[2*s], b_h[2*s+1]);
                        mma_bf16(cc, a_h[mf], b_l[2*s], b_l[2*s+1]);
                        mma_bf16(cc, a_l[mf], b_h[2*s], b_h[2*s+1]);
                    }
                }
            }
        }
        __syncthreads();
    }

#pragma unroll
    for (int mf = 0; mf < 2; mf++) {
        int r0 = wid * 32 + mf * 16 + (lane >> 2);
#pragma unroll
        for (int half = 0; half < 2; half++) {
            int rr = mbase + r0 + half * 8;
            if (rr < count) {
                int slot = off + rr;
                float w = g_wgt[slot];
                int   d = g_dest[slot];
                float* dst = g_ybuf + (size_t)d * HDIM + nb32 + (lane & 3) * 2;
#pragma unroll
                for (int nb8 = 0; nb8 < 4; nb8++) {
                    float2 o;
                    o.x = w * acc[mf][nb8][half * 2];
                    o.y = w * acc[mf][nb8][half * 2 + 1];
                    *(float2*)(dst + nb8 * 8) = o;
                }
            }
        }
    }
}

// ---------------- combine ----------------
__global__ void combine_kernel(float* __restrict__ out) {
    const int W = HDIM / 4;
    int i = blockIdx.x * blockDim.x + threadIdx.x;
    if (i >= TOK * W) return;
    int t = i / W, col = i % W;
    const float4* y = (const float4*)g_ybuf;
    float4 a = y[(size_t)(2 * t) * W + col];
    float4 b = y[(size_t)(2 * t + 1) * W + col];
    float4 o = { a.x + b.x, a.y + b.y, a.z + b.z, a.w + b.w };
    ((float4*)out)[i] = o;
}

// ---------------- launch ----------------
extern "C" void kernel_launch(void* const* d_in, const int* in_sizes, int n_in,
                              void* d_out, int out_size) {
    const float* x  = (const float*)d_in[0];   // [T, H]
    const float* gw = (const float*)d_in[1];   // [H, E]
    const float* w1 = (const float*)d_in[2];   // [E, H, I]
    const float* w3 = (const float*)d_in[3];   // [E, H, I]
    const float* w2 = (const float*)d_in[4];   // [E, I, H]
    float* out = (float*)d_out;                // [T, H]

    init_kernel<<<1, 32>>>();
    gate_kernel<<<TOK / 8, 256>>>(x, gw);
    scan_kernel<<<1, 1>>>();
    fill_kernel<<<TOK / 256, 256>>>();
    split_x_kernel<<<TOK, 128>>>(x);

    dim3 g1(IDIM / 32, NASSIGN / 128, NEXP);
    gemm1_kernel<<<g1, 128>>>(w1, w3);

    dim3 g2(HDIM / 32, NASSIGN / 128, NEXP);
    gemm2_kernel<<<g2, 128>>>(w2);

    combine_kernel<<<(TOK * (HDIM / 4)) / 256, 256>>>(out);
}